// round 1
// baseline (speedup 1.0000x reference)
#include <cuda_runtime.h>
#include <math.h>

// Problem constants
#define BATCH 4
#define SEQ   2048
#define DM    1024
#define NH    16
#define HD    64
#define NT    (BATCH*SEQ)   // 8192 tokens

// Scratch: Q/K/V in [B,H,S,HD] layout, ctx in [B,S,DM] layout.
__device__ float g_Q[(size_t)BATCH*NH*SEQ*HD];
__device__ float g_K[(size_t)BATCH*NH*SEQ*HD];
__device__ float g_V[(size_t)BATCH*NH*SEQ*HD];
__device__ float g_ctx[(size_t)NT*DM];

// ---------------------------------------------------------------------------
// Kernel 1: fused QKV projection.
// C[m, h*64+k] = sum_d X[m,d] * W[h,d,k], written into [B,H,S,HD] layout.
// Tile: BM=128, BN=64 (one head), BK=16. 256 threads, 8x4 micro-tile.
// ---------------------------------------------------------------------------
__global__ __launch_bounds__(256) void proj_kernel(
    const float* __restrict__ q_in, const float* __restrict__ k_in,
    const float* __restrict__ v_in,
    const float* __restrict__ Wq, const float* __restrict__ Wk,
    const float* __restrict__ Wv)
{
    const int which = blockIdx.z;
    const float* X = (which == 0) ? q_in : (which == 1) ? k_in : v_in;
    const float* W = ((which == 0) ? Wq : (which == 1) ? Wk : Wv)
                     + (size_t)blockIdx.y * DM * HD;
    float* Out = (which == 0) ? g_Q : (which == 1) ? g_K : g_V;

    __shared__ float As[16][132];  // k-major A tile, 128 rows (+4 pad)
    __shared__ float Bs[16][68];   // B tile [BK][BN] (+4 pad)

    const int tid = threadIdx.x;
    const int tx = tid & 15, ty = tid >> 4;
    const int m0 = blockIdx.x * 128;
    const int h  = blockIdx.y;

    float acc[8][4];
    #pragma unroll
    for (int i = 0; i < 8; i++)
        #pragma unroll
        for (int j = 0; j < 4; j++) acc[i][j] = 0.f;

    for (int d0 = 0; d0 < DM; d0 += 16) {
        // A tile: 128 x 16 = 512 float4, 2 per thread, store transposed (k-major)
        #pragma unroll
        for (int u = 0; u < 2; u++) {
            int f  = tid + u * 256;
            int r  = f >> 2;
            int c4 = f & 3;
            float4 v = *(const float4*)(X + (size_t)(m0 + r) * DM + d0 + 4 * c4);
            As[4*c4+0][r] = v.x; As[4*c4+1][r] = v.y;
            As[4*c4+2][r] = v.z; As[4*c4+3][r] = v.w;
        }
        // B tile: 16 x 64 = 256 float4, 1 per thread
        {
            int kk = tid >> 4;
            int c4 = tid & 15;
            float4 v = *(const float4*)(W + (size_t)(d0 + kk) * HD + 4 * c4);
            *(float4*)&Bs[kk][4*c4] = v;
        }
        __syncthreads();
        #pragma unroll
        for (int kk = 0; kk < 16; kk++) {
            float a[8], b[4];
            *(float4*)&a[0] = *(const float4*)&As[kk][8*ty];
            *(float4*)&a[4] = *(const float4*)&As[kk][8*ty + 4];
            *(float4*)&b[0] = *(const float4*)&Bs[kk][4*tx];
            #pragma unroll
            for (int i = 0; i < 8; i++)
                #pragma unroll
                for (int j = 0; j < 4; j++)
                    acc[i][j] += a[i] * b[j];
        }
        __syncthreads();
    }

    #pragma unroll
    for (int i = 0; i < 8; i++) {
        int m = m0 + 8*ty + i;
        int b = m / SEQ, s = m % SEQ;
        float* dst = Out + ((size_t)(b * NH + h) * SEQ + s) * HD + 4 * tx;
        *(float4*)dst = make_float4(acc[i][0], acc[i][1], acc[i][2], acc[i][3]);
    }
}

// ---------------------------------------------------------------------------
// Kernel 2: flash attention per (b,h). BR=BC=64 tiles, online softmax.
// 256 threads (16x16), each thread owns 4 rows x 4 cols.
// ---------------------------------------------------------------------------
#define BR 64
#define BC 64
#define SSTR 65   // smem row stride (65 = conflict-friendly, 65 % 32 == 1)
#define FLASH_SMEM (4 * BR * SSTR * sizeof(float))  // Qs,Ks,Vs,Ps = 66560 B

__global__ __launch_bounds__(256) void flash_kernel()
{
    extern __shared__ float fsh[];
    float* Qs = fsh;
    float* Ks = Qs + BR * SSTR;
    float* Vs = Ks + BC * SSTR;
    float* Ps = Vs + BC * SSTR;

    const int tid = threadIdx.x;
    const int tx = tid & 15, ty = tid >> 4;
    const int bh = blockIdx.y;              // b*NH + h
    const int s0 = blockIdx.x * BR;
    const float scale = 0.03125f;           // 1/sqrt(1024)

    const float* Qg = g_Q + (size_t)bh * SEQ * HD;
    const float* Kg = g_K + (size_t)bh * SEQ * HD;
    const float* Vg = g_V + (size_t)bh * SEQ * HD;

    // Load Q tile once: 64x64 = 1024 float4, 4 per thread
    #pragma unroll
    for (int u = 0; u < 4; u++) {
        int f  = tid + u * 256;
        int r  = f >> 4;
        int c4 = f & 15;
        float4 v = *(const float4*)(Qg + (size_t)(s0 + r) * HD + 4 * c4);
        Qs[r*SSTR + 4*c4+0] = v.x; Qs[r*SSTR + 4*c4+1] = v.y;
        Qs[r*SSTR + 4*c4+2] = v.z; Qs[r*SSTR + 4*c4+3] = v.w;
    }

    float m_i[4], l_i[4], o[4][4];
    #pragma unroll
    for (int i = 0; i < 4; i++) {
        m_i[i] = -1e30f; l_i[i] = 0.f;
        #pragma unroll
        for (int j = 0; j < 4; j++) o[i][j] = 0.f;
    }

    for (int j0 = 0; j0 < SEQ; j0 += BC) {
        __syncthreads();  // prior iteration done reading Ks/Vs/Ps
        #pragma unroll
        for (int u = 0; u < 4; u++) {
            int f  = tid + u * 256;
            int r  = f >> 4;
            int c4 = f & 15;
            float4 kv = *(const float4*)(Kg + (size_t)(j0 + r) * HD + 4 * c4);
            Ks[r*SSTR + 4*c4+0] = kv.x; Ks[r*SSTR + 4*c4+1] = kv.y;
            Ks[r*SSTR + 4*c4+2] = kv.z; Ks[r*SSTR + 4*c4+3] = kv.w;
            float4 vv = *(const float4*)(Vg + (size_t)(j0 + r) * HD + 4 * c4);
            Vs[r*SSTR + 4*c4+0] = vv.x; Vs[r*SSTR + 4*c4+1] = vv.y;
            Vs[r*SSTR + 4*c4+2] = vv.z; Vs[r*SSTR + 4*c4+3] = vv.w;
        }
        __syncthreads();

        // S = Q K^T (4x4 per thread over k=0..63)
        float s[4][4];
        #pragma unroll
        for (int i = 0; i < 4; i++)
            #pragma unroll
            for (int j = 0; j < 4; j++) s[i][j] = 0.f;
        #pragma unroll 4
        for (int k = 0; k < 64; k++) {
            float q[4], kv[4];
            #pragma unroll
            for (int i = 0; i < 4; i++) q[i]  = Qs[(4*ty + i)*SSTR + k];
            #pragma unroll
            for (int j = 0; j < 4; j++) kv[j] = Ks[(4*tx + j)*SSTR + k];
            #pragma unroll
            for (int i = 0; i < 4; i++)
                #pragma unroll
                for (int j = 0; j < 4; j++)
                    s[i][j] += q[i] * kv[j];
        }

        // Online softmax update (row groups = 16 lanes sharing ty)
        #pragma unroll
        for (int i = 0; i < 4; i++) {
            float mx = -1e30f;
            #pragma unroll
            for (int j = 0; j < 4; j++) { s[i][j] *= scale; mx = fmaxf(mx, s[i][j]); }
            #pragma unroll
            for (int off = 8; off; off >>= 1)
                mx = fmaxf(mx, __shfl_xor_sync(0xffffffffu, mx, off));
            float m_new = fmaxf(m_i[i], mx);
            float alpha = __expf(m_i[i] - m_new);
            float rs = 0.f;
            #pragma unroll
            for (int j = 0; j < 4; j++) {
                float p = __expf(s[i][j] - m_new);
                Ps[(4*ty + i)*SSTR + 4*tx + j] = p;
                rs += p;
            }
            #pragma unroll
            for (int off = 8; off; off >>= 1)
                rs += __shfl_xor_sync(0xffffffffu, rs, off);
            l_i[i] = l_i[i] * alpha + rs;
            m_i[i] = m_new;
            #pragma unroll
            for (int j = 0; j < 4; j++) o[i][j] *= alpha;
        }
        __syncthreads();  // Ps visible

        // O += P V
        #pragma unroll 4
        for (int kk = 0; kk < 64; kk++) {
            float p[4], v[4];
            #pragma unroll
            for (int i = 0; i < 4; i++) p[i] = Ps[(4*ty + i)*SSTR + kk];
            #pragma unroll
            for (int j = 0; j < 4; j++) v[j] = Vs[kk*SSTR + 4*tx + j];
            #pragma unroll
            for (int i = 0; i < 4; i++)
                #pragma unroll
                for (int j = 0; j < 4; j++)
                    o[i][j] += p[i] * v[j];
        }
    }

    // Write ctx[b, s, h*64 + c]
    const int b = bh >> 4, h = bh & 15;
    #pragma unroll
    for (int i = 0; i < 4; i++) {
        float inv = 1.f / l_i[i];
        int srow = s0 + 4*ty + i;
        float* dst = g_ctx + ((size_t)b * SEQ + srow) * DM + h * HD + 4 * tx;
        *(float4*)dst = make_float4(o[i][0]*inv, o[i][1]*inv, o[i][2]*inv, o[i][3]*inv);
    }
}

// ---------------------------------------------------------------------------
// Kernel 3: output projection. out[m,n] = sum_c ctx[m,c] * Wo[n,c] + bo[n]
// (C = A * B^T). BM=128, BN=64, BK=16, 8x4 micro.
// ---------------------------------------------------------------------------
__global__ __launch_bounds__(256) void out_kernel(
    const float* __restrict__ Wo, const float* __restrict__ bo,
    float* __restrict__ out)
{
    __shared__ float As[16][132];
    __shared__ float Bs[16][68];

    const int tid = threadIdx.x;
    const int tx = tid & 15, ty = tid >> 4;
    const int m0 = blockIdx.x * 128;
    const int n0 = blockIdx.y * 64;

    float acc[8][4];
    #pragma unroll
    for (int i = 0; i < 8; i++)
        #pragma unroll
        for (int j = 0; j < 4; j++) acc[i][j] = 0.f;

    for (int d0 = 0; d0 < DM; d0 += 16) {
        #pragma unroll
        for (int u = 0; u < 2; u++) {
            int f  = tid + u * 256;
            int r  = f >> 2;
            int c4 = f & 3;
            float4 v = *(const float4*)(g_ctx + (size_t)(m0 + r) * DM + d0 + 4 * c4);
            As[4*c4+0][r] = v.x; As[4*c4+1][r] = v.y;
            As[4*c4+2][r] = v.z; As[4*c4+3][r] = v.w;
        }
        // B tile from Wo[n,c]: 64 rows x 16 cols, transpose-store to [BK][BN]
        {
            int r  = tid >> 2;   // 0..63
            int c4 = tid & 3;    // 0..3
            float4 v = *(const float4*)(Wo + (size_t)(n0 + r) * DM + d0 + 4 * c4);
            Bs[4*c4+0][r] = v.x; Bs[4*c4+1][r] = v.y;
            Bs[4*c4+2][r] = v.z; Bs[4*c4+3][r] = v.w;
        }
        __syncthreads();
        #pragma unroll
        for (int kk = 0; kk < 16; kk++) {
            float a[8], b[4];
            *(float4*)&a[0] = *(const float4*)&As[kk][8*ty];
            *(float4*)&a[4] = *(const float4*)&As[kk][8*ty + 4];
            *(float4*)&b[0] = *(const float4*)&Bs[kk][4*tx];
            #pragma unroll
            for (int i = 0; i < 8; i++)
                #pragma unroll
                for (int j = 0; j < 4; j++)
                    acc[i][j] += a[i] * b[j];
        }
        __syncthreads();
    }

    float bb[4];
    #pragma unroll
    for (int j = 0; j < 4; j++) bb[j] = bo[n0 + 4*tx + j];

    #pragma unroll
    for (int i = 0; i < 8; i++) {
        int m = m0 + 8*ty + i;
        float* dst = out + (size_t)m * DM + n0 + 4 * tx;
        *(float4*)dst = make_float4(acc[i][0] + bb[0], acc[i][1] + bb[1],
                                    acc[i][2] + bb[2], acc[i][3] + bb[3]);
    }
}

// ---------------------------------------------------------------------------
extern "C" void kernel_launch(void* const* d_in, const int* in_sizes, int n_in,
                              void* d_out, int out_size)
{
    const float* q   = (const float*)d_in[0];
    const float* k   = (const float*)d_in[1];
    const float* v   = (const float*)d_in[2];
    const float* Wq  = (const float*)d_in[3];
    const float* Wk  = (const float*)d_in[4];
    const float* Wv  = (const float*)d_in[5];
    const float* Wo  = (const float*)d_in[6];
    const float* bo  = (const float*)d_in[7];
    float* out = (float*)d_out;

    // Opt-in to >48KB dynamic smem for the flash kernel (host-side, idempotent,
    // not a stream op — safe under graph capture).
    cudaFuncSetAttribute(flash_kernel,
                         cudaFuncAttributeMaxDynamicSharedMemorySize,
                         (int)FLASH_SMEM);

    dim3 gp(NT / 128, NH, 3);
    proj_kernel<<<gp, 256>>>(q, k, v, Wq, Wk, Wv);

    dim3 gf(SEQ / BR, BATCH * NH);
    flash_kernel<<<gf, 256, FLASH_SMEM>>>();

    dim3 go(NT / 128, DM / 64);
    out_kernel<<<go, 256>>>(Wo, bo, out);
}

// round 4
// speedup vs baseline: 2.4549x; 2.4549x over previous
#include <cuda_runtime.h>
#include <cuda_bf16.h>
#include <stdint.h>

#define BATCH 4
#define SEQ   2048
#define DM    1024
#define NH    16
#define HD    64
#define NT    (BATCH*SEQ)

__device__ float g_Q[(size_t)BATCH*NH*SEQ*HD];
__device__ float g_K[(size_t)BATCH*NH*SEQ*HD];
__device__ float g_V[(size_t)BATCH*NH*SEQ*HD];
__device__ float g_ctx[(size_t)NT*DM];

// ===========================================================================
// mma.sync / ldmatrix helpers (sm_80-level PTX; compiles for plain sm_103)
// ===========================================================================
__device__ __forceinline__ uint32_t smem_u32(const void* p){
    uint32_t a;
    asm("{ .reg .u64 t; cvta.to.shared.u64 t, %1; cvt.u32.u64 %0, t; }":"=r"(a):"l"(p));
    return a;
}
__device__ __forceinline__ void mma_bf16(float* c, const uint32_t* a, const uint32_t* b){
    asm volatile("mma.sync.aligned.m16n8k16.row.col.f32.bf16.bf16.f32 "
        "{%0,%1,%2,%3}, {%4,%5,%6,%7}, {%8,%9}, {%0,%1,%2,%3};"
        : "+f"(c[0]),"+f"(c[1]),"+f"(c[2]),"+f"(c[3])
        : "r"(a[0]),"r"(a[1]),"r"(a[2]),"r"(a[3]),"r"(b[0]),"r"(b[1]));
}
__device__ __forceinline__ void ldsm4(uint32_t* r, uint32_t a){
    asm volatile("ldmatrix.sync.aligned.m8n8.x4.shared.b16 {%0,%1,%2,%3}, [%4];"
        :"=r"(r[0]),"=r"(r[1]),"=r"(r[2]),"=r"(r[3]):"r"(a));
}
__device__ __forceinline__ void ldsm4t(uint32_t* r, uint32_t a){
    asm volatile("ldmatrix.sync.aligned.m8n8.x4.trans.shared.b16 {%0,%1,%2,%3}, [%4];"
        :"=r"(r[0]),"=r"(r[1]),"=r"(r[2]),"=r"(r[3]):"r"(a));
}
__device__ __forceinline__ uint32_t pack2(__nv_bfloat16 a, __nv_bfloat16 b){
    return (uint32_t)__bfloat16_as_ushort(a) | ((uint32_t)__bfloat16_as_ushort(b)<<16);
}
__device__ __forceinline__ void cvt_split4(float4 x, uint2& hi, uint2& lo){
    __nv_bfloat16 h0=__float2bfloat16(x.x), h1=__float2bfloat16(x.y),
                  h2=__float2bfloat16(x.z), h3=__float2bfloat16(x.w);
    __nv_bfloat16 l0=__float2bfloat16(x.x-__bfloat162float(h0)),
                  l1=__float2bfloat16(x.y-__bfloat162float(h1)),
                  l2=__float2bfloat16(x.z-__bfloat162float(h2)),
                  l3=__float2bfloat16(x.w-__bfloat162float(h3));
    hi = make_uint2(pack2(h0,h1), pack2(h2,h3));
    lo = make_uint2(pack2(l0,l1), pack2(l2,l3));
}
// A fragment m16k16 from row-major [m][k] tile (strideB bytes per row)
__device__ __forceinline__ void fragA(uint32_t* r, uint32_t base, int row0, int k0,
                                      int strideB, int lane){
    int row = row0 + (lane & 7) + ((lane >> 3) & 1) * 8;
    int kb  = (k0 + (lane >> 4) * 8) * 2;
    ldsm4(r, base + row*strideB + kb);
}
// B fragments (2 x n8, k16) from memory rows = n ([n][k] layout). r[0..1]=n0 grp, r[2..3]=n0+8 grp
__device__ __forceinline__ void fragB(uint32_t* r, uint32_t base, int n0, int k0,
                                      int strideB, int lane){
    int row = n0 + (lane & 7) + (lane >> 4) * 8;
    int kb  = (k0 + ((lane >> 3) & 1) * 8) * 2;
    ldsm4(r, base + row*strideB + kb);
}
// B fragments (2 x n8, k16) from memory rows = k ([k][n] layout) via .trans
__device__ __forceinline__ void fragBt(uint32_t* r, uint32_t base, int k0, int n0,
                                       int strideB, int lane){
    int row = k0 + (lane & 7) + ((lane >> 3) & 1) * 8;
    int nb  = (n0 + (lane >> 4) * 8) * 2;
    ldsm4t(r, base + row*strideB + nb);
}

// ===========================================================================
// GEMM kernels: 128x64 CTA tile, 8 warps (32x32 each), bf16x3, double buffer
// ===========================================================================
#define GSTRB 144                 // padded row stride bytes (72 bf16)
#define A_T   (128*GSTRB)         // 18432
#define B_T   (64*GSTRB)          // 9216
#define BUF   (2*A_T + 2*B_T)     // 55296: Ahi,Alo,Bhi,Blo
#define GEMM_SMEM (2*BUF)         // 110592

// QKV projection: C[m, h*64+n] = sum_d X[m,d] W[h][d,n]; W staged [d][n] -> fragBt
__global__ __launch_bounds__(256) void proj_tc(
    const float* __restrict__ q_in, const float* __restrict__ k_in,
    const float* __restrict__ v_in,
    const float* __restrict__ Wq, const float* __restrict__ Wk,
    const float* __restrict__ Wv)
{
    extern __shared__ char sm[];
    const uint32_t sb = smem_u32(sm);
    const int tid = threadIdx.x, lane = tid & 31, wid = tid >> 5;
    const int wr = wid >> 1, wc = wid & 1;
    const int which = blockIdx.z, h = blockIdx.y, m0 = blockIdx.x * 128;
    const float* X = which == 0 ? q_in : which == 1 ? k_in : v_in;
    const float* W = (which == 0 ? Wq : which == 1 ? Wk : Wv) + (size_t)h * DM * HD;
    float* Out = which == 0 ? g_Q : which == 1 ? g_K : g_V;

    auto stage = [&](int d0, int buf){
        char* bp = sm + buf * BUF;
        #pragma unroll
        for (int i = 0; i < 8; i++){                     // A: 128x64
            int idx = tid + 256*i;
            int r = idx >> 4, c = (idx & 15) * 4;
            float4 x = *(const float4*)(X + (size_t)(m0 + r)*DM + d0 + c);
            uint2 hi, lo; cvt_split4(x, hi, lo);
            *(uint2*)(bp + r*GSTRB + c*2)        = hi;
            *(uint2*)(bp + A_T + r*GSTRB + c*2)  = lo;
        }
        #pragma unroll
        for (int i = 0; i < 4; i++){                     // W: 64(d) x 64(n)
            int idx = tid + 256*i;
            int r = idx >> 4, c = (idx & 15) * 4;
            float4 x = *(const float4*)(W + (size_t)(d0 + r)*HD + c);
            uint2 hi, lo; cvt_split4(x, hi, lo);
            *(uint2*)(bp + 2*A_T + r*GSTRB + c*2)       = hi;
            *(uint2*)(bp + 2*A_T + B_T + r*GSTRB + c*2) = lo;
        }
    };

    float c[2][4][4] = {};
    stage(0, 0);
    __syncthreads();
    for (int ch = 0; ch < DM/64; ch++){
        int buf = ch & 1;
        if (ch + 1 < DM/64) stage((ch + 1)*64, buf ^ 1);
        uint32_t ab = sb + buf*BUF, bb = ab + 2*A_T;
        #pragma unroll
        for (int kk = 0; kk < 4; kk++){
            int k0 = kk * 16;
            uint32_t ah[2][4], al[2][4], bh[2][4], bl[2][4];
            fragA(ah[0], ab,        32*wr,      k0, GSTRB, lane);
            fragA(ah[1], ab,        32*wr + 16, k0, GSTRB, lane);
            fragA(al[0], ab + A_T,  32*wr,      k0, GSTRB, lane);
            fragA(al[1], ab + A_T,  32*wr + 16, k0, GSTRB, lane);
            fragBt(bh[0], bb,       k0, 32*wc,      GSTRB, lane);
            fragBt(bh[1], bb,       k0, 32*wc + 16, GSTRB, lane);
            fragBt(bl[0], bb + B_T, k0, 32*wc,      GSTRB, lane);
            fragBt(bl[1], bb + B_T, k0, 32*wc + 16, GSTRB, lane);
            #pragma unroll
            for (int mg = 0; mg < 2; mg++)
                #pragma unroll
                for (int n = 0; n < 4; n++){
                    const uint32_t* bhp = &bh[n>>1][(n&1)*2];
                    const uint32_t* blp = &bl[n>>1][(n&1)*2];
                    mma_bf16(c[mg][n], ah[mg], bhp);
                    mma_bf16(c[mg][n], al[mg], bhp);
                    mma_bf16(c[mg][n], ah[mg], blp);
                }
        }
        __syncthreads();
    }
    #pragma unroll
    for (int mg = 0; mg < 2; mg++)
        #pragma unroll
        for (int n = 0; n < 4; n++){
            int col = 32*wc + 8*n + (lane & 3)*2;
            int mA = m0 + 32*wr + 16*mg + (lane >> 2);
            int bA = mA / SEQ, sA = mA % SEQ;
            *(float2*)(Out + ((size_t)(bA*NH + h)*SEQ + sA)*HD + col)
                = make_float2(c[mg][n][0], c[mg][n][1]);
            int mB = mA + 8;
            int bB = mB / SEQ, sB = mB % SEQ;
            *(float2*)(Out + ((size_t)(bB*NH + h)*SEQ + sB)*HD + col)
                = make_float2(c[mg][n][2], c[mg][n][3]);
        }
}

// Output projection: out[m,n] = sum_c ctx[m,c]*Wo[n,c] + bo[n]; Wo rows=n -> fragB
__global__ __launch_bounds__(256) void out_tc(
    const float* __restrict__ Wo, const float* __restrict__ bo,
    float* __restrict__ out)
{
    extern __shared__ char sm[];
    const uint32_t sb = smem_u32(sm);
    const int tid = threadIdx.x, lane = tid & 31, wid = tid >> 5;
    const int wr = wid >> 1, wc = wid & 1;
    const int m0 = blockIdx.x * 128, n0 = blockIdx.y * 64;

    auto stage = [&](int d0, int buf){
        char* bp = sm + buf * BUF;
        #pragma unroll
        for (int i = 0; i < 8; i++){
            int idx = tid + 256*i;
            int r = idx >> 4, c = (idx & 15) * 4;
            float4 x = *(const float4*)(g_ctx + (size_t)(m0 + r)*DM + d0 + c);
            uint2 hi, lo; cvt_split4(x, hi, lo);
            *(uint2*)(bp + r*GSTRB + c*2)       = hi;
            *(uint2*)(bp + A_T + r*GSTRB + c*2) = lo;
        }
        #pragma unroll
        for (int i = 0; i < 4; i++){                    // Wo: 64(n) x 64(k)
            int idx = tid + 256*i;
            int r = idx >> 4, c = (idx & 15) * 4;
            float4 x = *(const float4*)(Wo + (size_t)(n0 + r)*DM + d0 + c);
            uint2 hi, lo; cvt_split4(x, hi, lo);
            *(uint2*)(bp + 2*A_T + r*GSTRB + c*2)       = hi;
            *(uint2*)(bp + 2*A_T + B_T + r*GSTRB + c*2) = lo;
        }
    };

    float c[2][4][4] = {};
    stage(0, 0);
    __syncthreads();
    for (int ch = 0; ch < DM/64; ch++){
        int buf = ch & 1;
        if (ch + 1 < DM/64) stage((ch + 1)*64, buf ^ 1);
        uint32_t ab = sb + buf*BUF, bb = ab + 2*A_T;
        #pragma unroll
        for (int kk = 0; kk < 4; kk++){
            int k0 = kk * 16;
            uint32_t ah[2][4], al[2][4], bh[2][4], bl[2][4];
            fragA(ah[0], ab,        32*wr,      k0, GSTRB, lane);
            fragA(ah[1], ab,        32*wr + 16, k0, GSTRB, lane);
            fragA(al[0], ab + A_T,  32*wr,      k0, GSTRB, lane);
            fragA(al[1], ab + A_T,  32*wr + 16, k0, GSTRB, lane);
            fragB(bh[0], bb,        32*wc,      k0, GSTRB, lane);
            fragB(bh[1], bb,        32*wc + 16, k0, GSTRB, lane);
            fragB(bl[0], bb + B_T,  32*wc,      k0, GSTRB, lane);
            fragB(bl[1], bb + B_T,  32*wc + 16, k0, GSTRB, lane);
            #pragma unroll
            for (int mg = 0; mg < 2; mg++)
                #pragma unroll
                for (int n = 0; n < 4; n++){
                    const uint32_t* bhp = &bh[n>>1][(n&1)*2];
                    const uint32_t* blp = &bl[n>>1][(n&1)*2];
                    mma_bf16(c[mg][n], ah[mg], bhp);
                    mma_bf16(c[mg][n], al[mg], bhp);
                    mma_bf16(c[mg][n], ah[mg], blp);
                }
        }
        __syncthreads();
    }
    #pragma unroll
    for (int mg = 0; mg < 2; mg++)
        #pragma unroll
        for (int n = 0; n < 4; n++){
            int col = n0 + 32*wc + 8*n + (lane & 3)*2;
            float b0 = bo[col], b1 = bo[col + 1];
            int mA = m0 + 32*wr + 16*mg + (lane >> 2);
            *(float2*)(out + (size_t)mA*DM + col)
                = make_float2(c[mg][n][0] + b0, c[mg][n][1] + b1);
            *(float2*)(out + (size_t)(mA + 8)*DM + col)
                = make_float2(c[mg][n][2] + b0, c[mg][n][3] + b1);
        }
}

// ===========================================================================
// Flash attention on mma.sync: BR=BC=64, 8 warps, warp S-tile 16x32
// ===========================================================================
#define FSTRB 144
#define FT    (64*FSTRB)           // 9216 per tile
// smem: QHI 0, QLO FT, KHI 2FT, KLO 3FT, VHI 4FT, VLO 5FT, RED 6FT (1KB)
#define FLASH_SMEM (6*FT + 1024)
#define OB_STRIDE 68               // fp32 O-combine buffer stride (aliases K tiles)

__global__ __launch_bounds__(256) void flash_tc()
{
    extern __shared__ char sm[];
    const uint32_t sb = smem_u32(sm);
    float* red = (float*)(sm + 6*FT);        // [0..127]=max [128..255]=sum, idx wc*64+row
    const int tid = threadIdx.x, lane = tid & 31, wid = tid >> 5;
    const int wq = wid >> 1, wc = wid & 1;
    const int bh = blockIdx.y, s0 = blockIdx.x * 64;
    const float scale = 0.03125f;
    const float* Qg = g_Q + (size_t)bh * SEQ * HD;
    const float* Kg = g_K + (size_t)bh * SEQ * HD;
    const float* Vg = g_V + (size_t)bh * SEQ * HD;

    auto stage64 = [&](const float* src, int offh, int offl){
        #pragma unroll
        for (int i = 0; i < 4; i++){
            int idx = tid + 256*i;
            int r = idx >> 4, c = (idx & 15) * 4;
            float4 x = *(const float4*)(src + r*HD + c);
            uint2 hi, lo; cvt_split4(x, hi, lo);
            *(uint2*)(sm + offh + r*FSTRB + c*2) = hi;
            *(uint2*)(sm + offl + r*FSTRB + c*2) = lo;
        }
    };

    stage64(Qg + (size_t)s0*HD, 0, FT);

    const int row0 = 16*wq + (lane >> 2);    // thread's first S/O row
    float m_i[2] = {-1e30f, -1e30f}, l_i[2] = {0.f, 0.f};
    float oc[8][4] = {};

    for (int j0 = 0; j0 < SEQ; j0 += 64){
        __syncthreads();                      // prev iter done with K/V (and Q staged)
        stage64(Kg + (size_t)j0*HD, 2*FT, 3*FT);
        stage64(Vg + (size_t)j0*HD, 4*FT, 5*FT);
        __syncthreads();

        // ---- S = Q K^T (warp: rows 16wq..+15, t-cols 32wc..+31) ----
        float sc[4][4] = {};
        #pragma unroll
        for (int kk = 0; kk < 4; kk++){
            int k0 = kk * 16;
            uint32_t qh[4], ql[4], kh[2][4], kl[2][4];
            fragA(qh, sb,        16*wq, k0, FSTRB, lane);
            fragA(ql, sb + FT,   16*wq, k0, FSTRB, lane);
            fragB(kh[0], sb + 2*FT, 32*wc,      k0, FSTRB, lane);
            fragB(kh[1], sb + 2*FT, 32*wc + 16, k0, FSTRB, lane);
            fragB(kl[0], sb + 3*FT, 32*wc,      k0, FSTRB, lane);
            fragB(kl[1], sb + 3*FT, 32*wc + 16, k0, FSTRB, lane);
            #pragma unroll
            for (int n = 0; n < 4; n++){
                const uint32_t* bhp = &kh[n>>1][(n&1)*2];
                const uint32_t* blp = &kl[n>>1][(n&1)*2];
                mma_bf16(sc[n], qh, bhp);
                mma_bf16(sc[n], ql, bhp);
                mma_bf16(sc[n], qh, blp);
            }
        }
        // ---- online softmax ----
        float mx0 = -1e30f, mx1 = -1e30f;
        #pragma unroll
        for (int n = 0; n < 4; n++){
            #pragma unroll
            for (int r = 0; r < 4; r++) sc[n][r] *= scale;
            mx0 = fmaxf(mx0, fmaxf(sc[n][0], sc[n][1]));
            mx1 = fmaxf(mx1, fmaxf(sc[n][2], sc[n][3]));
        }
        #pragma unroll
        for (int off = 1; off <= 2; off <<= 1){
            mx0 = fmaxf(mx0, __shfl_xor_sync(0xffffffffu, mx0, off));
            mx1 = fmaxf(mx1, __shfl_xor_sync(0xffffffffu, mx1, off));
        }
        if ((lane & 3) == 0){ red[wc*64 + row0] = mx0; red[wc*64 + row0 + 8] = mx1; }
        __syncthreads();
        float gm0 = fmaxf(red[row0],     red[64 + row0]);
        float gm1 = fmaxf(red[row0 + 8], red[64 + row0 + 8]);
        float mn0 = fmaxf(m_i[0], gm0), mn1 = fmaxf(m_i[1], gm1);
        float al0 = __expf(m_i[0] - mn0), al1 = __expf(m_i[1] - mn1);
        m_i[0] = mn0; m_i[1] = mn1;

        uint32_t ph[2][4], pl[2][4];
        float rs0 = 0.f, rs1 = 0.f;
        #pragma unroll
        for (int g = 0; g < 2; g++){
            float p[2][4];   // [f][r] for the two n-frags of this k16 group
            #pragma unroll
            for (int f = 0; f < 2; f++){
                int n = 2*g + f;
                p[f][0] = __expf(sc[n][0] - mn0);
                p[f][1] = __expf(sc[n][1] - mn0);
                p[f][2] = __expf(sc[n][2] - mn1);
                p[f][3] = __expf(sc[n][3] - mn1);
                rs0 += p[f][0] + p[f][1];
                rs1 += p[f][2] + p[f][3];
            }
            // pack into A-frag order: reg0={f0 c0,c1} reg1={f0 c2,c3} reg2={f1 c0,c1} reg3={f1 c2,c3}
            #pragma unroll
            for (int f = 0; f < 2; f++){
                __nv_bfloat16 h0=__float2bfloat16(p[f][0]), h1=__float2bfloat16(p[f][1]),
                              h2=__float2bfloat16(p[f][2]), h3=__float2bfloat16(p[f][3]);
                ph[g][2*f]   = pack2(h0, h1);
                ph[g][2*f+1] = pack2(h2, h3);
                pl[g][2*f]   = pack2(__float2bfloat16(p[f][0]-__bfloat162float(h0)),
                                     __float2bfloat16(p[f][1]-__bfloat162float(h1)));
                pl[g][2*f+1] = pack2(__float2bfloat16(p[f][2]-__bfloat162float(h2)),
                                     __float2bfloat16(p[f][3]-__bfloat162float(h3)));
            }
        }
        #pragma unroll
        for (int off = 1; off <= 2; off <<= 1){
            rs0 += __shfl_xor_sync(0xffffffffu, rs0, off);
            rs1 += __shfl_xor_sync(0xffffffffu, rs1, off);
        }
        if ((lane & 3) == 0){ red[128 + wc*64 + row0] = rs0; red[128 + wc*64 + row0 + 8] = rs1; }
        __syncthreads();
        l_i[0] = l_i[0]*al0 + red[128 + row0]     + red[128 + 64 + row0];
        l_i[1] = l_i[1]*al1 + red[128 + row0 + 8] + red[128 + 64 + row0 + 8];

        // rescale O, then O += P V (partial over this warp's t-half)
        #pragma unroll
        for (int f = 0; f < 8; f++){
            oc[f][0] *= al0; oc[f][1] *= al0; oc[f][2] *= al1; oc[f][3] *= al1;
        }
        #pragma unroll
        for (int g = 0; g < 2; g++){
            int t0 = 32*wc + 16*g;
            #pragma unroll
            for (int vg = 0; vg < 4; vg++){
                uint32_t vh[4], vl[4];
                fragBt(vh, sb + 4*FT, t0, 16*vg, FSTRB, lane);
                fragBt(vl, sb + 5*FT, t0, 16*vg, FSTRB, lane);
                mma_bf16(oc[2*vg],   ph[g], &vh[0]);
                mma_bf16(oc[2*vg],   pl[g], &vh[0]);
                mma_bf16(oc[2*vg],   ph[g], &vl[0]);
                mma_bf16(oc[2*vg+1], ph[g], &vh[2]);
                mma_bf16(oc[2*vg+1], pl[g], &vh[2]);
                mma_bf16(oc[2*vg+1], ph[g], &vl[2]);
            }
        }
    }

    // combine the two wc halves and write ctx
    __syncthreads();
    float* ob = (float*)(sm + 2*FT);
    if (wc == 1){
        #pragma unroll
        for (int f = 0; f < 8; f++){
            int col = 8*f + (lane & 3)*2;
            *(float2*)&ob[row0*OB_STRIDE + col]       = make_float2(oc[f][0], oc[f][1]);
            *(float2*)&ob[(row0 + 8)*OB_STRIDE + col] = make_float2(oc[f][2], oc[f][3]);
        }
    }
    __syncthreads();
    if (wc == 0){
        float inv0 = 1.f / l_i[0], inv1 = 1.f / l_i[1];
        int b = bh >> 4, h = bh & 15;
        #pragma unroll
        for (int f = 0; f < 8; f++){
            int col = 8*f + (lane & 3)*2;
            float2 p0 = *(float2*)&ob[row0*OB_STRIDE + col];
            float2 p1 = *(float2*)&ob[(row0 + 8)*OB_STRIDE + col];
            *(float2*)(g_ctx + ((size_t)b*SEQ + s0 + row0)*DM + h*HD + col)
                = make_float2((oc[f][0] + p0.x)*inv0, (oc[f][1] + p0.y)*inv0);
            *(float2*)(g_ctx + ((size_t)b*SEQ + s0 + row0 + 8)*DM + h*HD + col)
                = make_float2((oc[f][2] + p1.x)*inv1, (oc[f][3] + p1.y)*inv1);
        }
    }
}

// ===========================================================================
extern "C" void kernel_launch(void* const* d_in, const int* in_sizes, int n_in,
                              void* d_out, int out_size)
{
    const float* q  = (const float*)d_in[0];
    const float* k  = (const float*)d_in[1];
    const float* v  = (const float*)d_in[2];
    const float* Wq = (const float*)d_in[3];
    const float* Wk = (const float*)d_in[4];
    const float* Wv = (const float*)d_in[5];
    const float* Wo = (const float*)d_in[6];
    const float* bo = (const float*)d_in[7];
    float* out = (float*)d_out;

    cudaFuncSetAttribute(proj_tc,  cudaFuncAttributeMaxDynamicSharedMemorySize, GEMM_SMEM);
    cudaFuncSetAttribute(out_tc,   cudaFuncAttributeMaxDynamicSharedMemorySize, GEMM_SMEM);
    cudaFuncSetAttribute(flash_tc, cudaFuncAttributeMaxDynamicSharedMemorySize, FLASH_SMEM);

    dim3 gp(NT/128, NH, 3);
    proj_tc<<<gp, 256, GEMM_SMEM>>>(q, k, v, Wq, Wk, Wv);

    dim3 gf(SEQ/64, BATCH*NH);
    flash_tc<<<gf, 256, FLASH_SMEM>>>();

    dim3 go(NT/128, DM/64);
    out_tc<<<go, 256, GEMM_SMEM>>>(Wo, bo, out);
}

// round 5
// speedup vs baseline: 2.8078x; 1.1438x over previous
#include <cuda_runtime.h>
#include <cuda_bf16.h>
#include <stdint.h>

#define BATCH 4
#define SEQ   2048
#define DM    1024
#define NH    16
#define HD    64
#define NT    (BATCH*SEQ)

// ---- pre-split bf16 scratch (hi/lo pairs) ----
__device__ __nv_bfloat16 g_Xh[(size_t)3*NT*DM],  g_Xl[(size_t)3*NT*DM];   // inputs
__device__ __nv_bfloat16 g_Wth[(size_t)3*DM*DM], g_Wtl[(size_t)3*DM*DM];  // QKV W, [which][d][h*64+k]
__device__ __nv_bfloat16 g_Woh[(size_t)DM*DM],   g_Wol[(size_t)DM*DM];    // Wo [n][k]
__device__ __nv_bfloat16 g_Qh[(size_t)NT*DM], g_Ql[(size_t)NT*DM];        // [b,h,s,hd]
__device__ __nv_bfloat16 g_Kh[(size_t)NT*DM], g_Kl[(size_t)NT*DM];
__device__ __nv_bfloat16 g_Vh[(size_t)NT*DM], g_Vl[(size_t)NT*DM];
__device__ __nv_bfloat16 g_Ch[(size_t)NT*DM], g_Cl[(size_t)NT*DM];        // ctx [b,s,dm]

// ===========================================================================
// helpers
// ===========================================================================
__device__ __forceinline__ uint32_t smem_u32(const void* p){
    uint32_t a;
    asm("{ .reg .u64 t; cvta.to.shared.u64 t, %1; cvt.u32.u64 %0, t; }":"=r"(a):"l"(p));
    return a;
}
__device__ __forceinline__ void mma_bf16(float* c, const uint32_t* a, const uint32_t* b){
    asm volatile("mma.sync.aligned.m16n8k16.row.col.f32.bf16.bf16.f32 "
        "{%0,%1,%2,%3}, {%4,%5,%6,%7}, {%8,%9}, {%0,%1,%2,%3};"
        : "+f"(c[0]),"+f"(c[1]),"+f"(c[2]),"+f"(c[3])
        : "r"(a[0]),"r"(a[1]),"r"(a[2]),"r"(a[3]),"r"(b[0]),"r"(b[1]));
}
__device__ __forceinline__ void ldsm4(uint32_t* r, uint32_t a){
    asm volatile("ldmatrix.sync.aligned.m8n8.x4.shared.b16 {%0,%1,%2,%3}, [%4];"
        :"=r"(r[0]),"=r"(r[1]),"=r"(r[2]),"=r"(r[3]):"r"(a));
}
__device__ __forceinline__ void ldsm4t(uint32_t* r, uint32_t a){
    asm volatile("ldmatrix.sync.aligned.m8n8.x4.trans.shared.b16 {%0,%1,%2,%3}, [%4];"
        :"=r"(r[0]),"=r"(r[1]),"=r"(r[2]),"=r"(r[3]):"r"(a));
}
__device__ __forceinline__ void cpa16(uint32_t s, const void* g){
    asm volatile("cp.async.cg.shared.global [%0], [%1], 16;" :: "r"(s), "l"(g));
}
__device__ __forceinline__ void cpa_commit(){ asm volatile("cp.async.commit_group;"); }
template<int N> __device__ __forceinline__ void cpa_wait(){
    asm volatile("cp.async.wait_group %0;" :: "n"(N));
}
__device__ __forceinline__ uint32_t pack2(__nv_bfloat16 a, __nv_bfloat16 b){
    return (uint32_t)__bfloat16_as_ushort(a) | ((uint32_t)__bfloat16_as_ushort(b)<<16);
}
__device__ __forceinline__ void cvt_split4(float4 x, uint2& hi, uint2& lo){
    __nv_bfloat16 h0=__float2bfloat16(x.x), h1=__float2bfloat16(x.y),
                  h2=__float2bfloat16(x.z), h3=__float2bfloat16(x.w);
    __nv_bfloat16 l0=__float2bfloat16(x.x-__bfloat162float(h0)),
                  l1=__float2bfloat16(x.y-__bfloat162float(h1)),
                  l2=__float2bfloat16(x.z-__bfloat162float(h2)),
                  l3=__float2bfloat16(x.w-__bfloat162float(h3));
    hi = make_uint2(pack2(h0,h1), pack2(h2,h3));
    lo = make_uint2(pack2(l0,l1), pack2(l2,l3));
}
__device__ __forceinline__ void store_split2(__nv_bfloat16* H, __nv_bfloat16* L,
                                             size_t off, float a, float b){
    __nv_bfloat16 h0=__float2bfloat16(a), h1=__float2bfloat16(b);
    *(uint32_t*)(H+off) = pack2(h0,h1);
    *(uint32_t*)(L+off) = pack2(__float2bfloat16(a-__bfloat162float(h0)),
                                __float2bfloat16(b-__bfloat162float(h1)));
}
// A fragment m16k16 from row-major [m][k] tile
__device__ __forceinline__ void fragA(uint32_t* r, uint32_t base, int row0, int k0,
                                      int strideB, int lane){
    int row = row0 + (lane & 7) + ((lane >> 3) & 1) * 8;
    int kb  = (k0 + (lane >> 4) * 8) * 2;
    ldsm4(r, base + row*strideB + kb);
}
// B fragments (2 x n8, k16), memory rows = n
__device__ __forceinline__ void fragB(uint32_t* r, uint32_t base, int n0, int k0,
                                      int strideB, int lane){
    int row = n0 + (lane & 7) + (lane >> 4) * 8;
    int kb  = (k0 + ((lane >> 3) & 1) * 8) * 2;
    ldsm4(r, base + row*strideB + kb);
}
// B fragments (2 x n8, k16), memory rows = k, via trans
__device__ __forceinline__ void fragBt(uint32_t* r, uint32_t base, int k0, int n0,
                                       int strideB, int lane){
    int row = k0 + (lane & 7) + ((lane >> 3) & 1) * 8;
    int nb  = (n0 + (lane >> 4) * 8) * 2;
    ldsm4t(r, base + row*strideB + nb);
}

// ===========================================================================
// prep: split everything to bf16 hi/lo once. grid (128,1,7)
// ===========================================================================
__global__ __launch_bounds__(256) void prep(
    const float* __restrict__ q, const float* __restrict__ kin,
    const float* __restrict__ vin,
    const float* __restrict__ Wq, const float* __restrict__ Wk,
    const float* __restrict__ Wv, const float* __restrict__ Wo)
{
    int z = blockIdx.z;
    size_t t0 = (size_t)blockIdx.x*blockDim.x + threadIdx.x;
    size_t nth = (size_t)gridDim.x*blockDim.x;
    if (z < 3){
        const float* X = z==0?q:z==1?kin:vin;
        __nv_bfloat16* H = g_Xh + (size_t)z*NT*DM;
        __nv_bfloat16* L = g_Xl + (size_t)z*NT*DM;
        size_t n4 = (size_t)NT*DM/4;
        for (size_t i = t0; i < n4; i += nth){
            float4 x = *(const float4*)(X + 4*i);
            uint2 hi, lo; cvt_split4(x, hi, lo);
            *(uint2*)(H + 4*i) = hi; *(uint2*)(L + 4*i) = lo;
        }
    } else if (z == 3){
        size_t n4 = (size_t)DM*DM/4;
        for (size_t i = t0; i < n4; i += nth){
            float4 x = *(const float4*)(Wo + 4*i);
            uint2 hi, lo; cvt_split4(x, hi, lo);
            *(uint2*)(g_Woh + 4*i) = hi; *(uint2*)(g_Wol + 4*i) = lo;
        }
    } else {
        int w = z - 4;
        const float* W = w==0?Wq:w==1?Wk:Wv;
        size_t n = (size_t)NH*DM*16;                 // (h,d,k4)
        for (size_t i = t0; i < n; i += nth){
            int h = (int)(i >> 14), d = (int)((i >> 4) & 1023), k4 = (int)(i & 15);
            float4 x = *(const float4*)(W + (((size_t)h*DM + d)*HD + k4*4));
            uint2 hi, lo; cvt_split4(x, hi, lo);
            size_t o = ((size_t)w*DM + d)*DM + h*HD + k4*4;
            *(uint2*)(g_Wth + o) = hi; *(uint2*)(g_Wtl + o) = lo;
        }
    }
}

// ===========================================================================
// proj: C[8192,1024] = X[which] @ Wt[which], 128x128 tiles, cp.async 2-stage
// ===========================================================================
#define PASTR 144
#define PBSTR 272
#define PA_T  (128*PASTR)          // 18432
#define PB_T  (64*PBSTR)           // 17408
#define PSTG  (2*PA_T + 2*PB_T)    // 71680
#define PROJ_SMEM (2*PSTG)         // 143360

__global__ __launch_bounds__(256) void proj_tc()
{
    extern __shared__ char sm[];
    const uint32_t sb = smem_u32(sm);
    const int tid = threadIdx.x, lane = tid & 31, wid = tid >> 5;
    const int wr = wid >> 1, wc = wid & 1;
    const int which = blockIdx.z, m0 = blockIdx.x*128, n0 = blockIdx.y*128;
    const __nv_bfloat16* Ah_g = g_Xh  + (size_t)which*NT*DM;
    const __nv_bfloat16* Al_g = g_Xl  + (size_t)which*NT*DM;
    const __nv_bfloat16* Bh_g = g_Wth + (size_t)which*DM*DM;
    const __nv_bfloat16* Bl_g = g_Wtl + (size_t)which*DM*DM;

    auto stage = [&](int ch, int buf){
        int d0 = ch*64;
        uint32_t s = sb + buf*PSTG;
        #pragma unroll
        for (int i = 0; i < 4; i++){
            int idx = tid + 256*i, r = idx >> 3, c = idx & 7;
            cpa16(s + r*PASTR + c*16,        Ah_g + (size_t)(m0+r)*DM + d0 + c*8);
            cpa16(s + PA_T + r*PASTR + c*16, Al_g + (size_t)(m0+r)*DM + d0 + c*8);
        }
        #pragma unroll
        for (int i = 0; i < 4; i++){
            int idx = tid + 256*i, r = idx >> 4, c = idx & 15;
            cpa16(s + 2*PA_T + r*PBSTR + c*16,        Bh_g + (size_t)(d0+r)*DM + n0 + c*8);
            cpa16(s + 2*PA_T + PB_T + r*PBSTR + c*16, Bl_g + (size_t)(d0+r)*DM + n0 + c*8);
        }
        cpa_commit();
    };

    float acc[2][8][4] = {};
    stage(0,0); stage(1,1);
    for (int ch = 0; ch < 16; ch++){
        if (ch+1 < 16) cpa_wait<1>(); else cpa_wait<0>();
        __syncthreads();
        uint32_t ab = sb + (ch&1)*PSTG, bb = ab + 2*PA_T;
        #pragma unroll
        for (int kk = 0; kk < 4; kk++){
            int k0 = 16*kk;
            uint32_t ah[2][4], al[2][4], bh[4][4], bl[4][4];
            fragA(ah[0], ab,        32*wr,    k0, PASTR, lane);
            fragA(ah[1], ab,        32*wr+16, k0, PASTR, lane);
            fragA(al[0], ab+PA_T,   32*wr,    k0, PASTR, lane);
            fragA(al[1], ab+PA_T,   32*wr+16, k0, PASTR, lane);
            #pragma unroll
            for (int g = 0; g < 4; g++){
                fragBt(bh[g], bb,      k0, 64*wc+16*g, PBSTR, lane);
                fragBt(bl[g], bb+PB_T, k0, 64*wc+16*g, PBSTR, lane);
            }
            #pragma unroll
            for (int mg = 0; mg < 2; mg++)
                #pragma unroll
                for (int nf = 0; nf < 8; nf++){
                    const uint32_t* bhp = &bh[nf>>1][(nf&1)*2];
                    const uint32_t* blp = &bl[nf>>1][(nf&1)*2];
                    mma_bf16(acc[mg][nf], ah[mg], bhp);
                    mma_bf16(acc[mg][nf], al[mg], bhp);
                    mma_bf16(acc[mg][nf], ah[mg], blp);
                }
        }
        __syncthreads();
        if (ch+2 < 16) stage(ch+2, ch&1);
    }
    __nv_bfloat16* OH = which==0 ? g_Qh : which==1 ? g_Kh : g_Vh;
    __nv_bfloat16* OL = which==0 ? g_Ql : which==1 ? g_Kl : g_Vl;
    #pragma unroll
    for (int mg = 0; mg < 2; mg++)
        #pragma unroll
        for (int nf = 0; nf < 8; nf++){
            int n = n0 + 64*wc + 8*nf + (lane&3)*2;
            int h = n >> 6, kcol = n & 63;
            int mA = m0 + 32*wr + 16*mg + (lane>>2);
            int bA = mA / SEQ, sA = mA % SEQ;
            size_t oA = ((size_t)(bA*NH + h)*SEQ + sA)*HD + kcol;
            store_split2(OH, OL, oA,            acc[mg][nf][0], acc[mg][nf][1]);
            store_split2(OH, OL, oA + 8*(size_t)HD, acc[mg][nf][2], acc[mg][nf][3]);
        }
}

// ===========================================================================
// flash: BR=128, warp = 16 full rows; pre-split bf16 K/V; cp.async 2-stage
// ===========================================================================
#define FB     144
#define FTILE  (64*FB)        // 9216
#define FBUF   (4*FTILE)      // 36864: Kh,Kl,Vh,Vl
#define FLASH_SMEM (2*FBUF)   // 73728
#define NIT (SEQ/64)

__global__ __launch_bounds__(256) void flash_tc()
{
    extern __shared__ char sm[];
    const uint32_t sb = smem_u32(sm);
    const int tid = threadIdx.x, lane = tid & 31, wq = tid >> 5;
    const int bh = blockIdx.y, s0 = blockIdx.x*128;
    const size_t base = (size_t)bh*SEQ*HD;
    const __nv_bfloat16 *Khg=g_Kh+base, *Klg=g_Kl+base, *Vhg=g_Vh+base, *Vlg=g_Vl+base;

    // stage Q hi/lo (128x64) into first 36KB, extract frags, then reuse space
    {
        const __nv_bfloat16 *Qh = g_Qh + base + (size_t)s0*HD;
        const __nv_bfloat16 *Ql = g_Ql + base + (size_t)s0*HD;
        #pragma unroll
        for (int i = 0; i < 4; i++){
            int idx = tid + 256*i, r = idx >> 3, c = idx & 7;
            cpa16(sb + r*FB + c*16,            Qh + (size_t)r*HD + c*8);
            cpa16(sb + 2*FTILE + r*FB + c*16,  Ql + (size_t)r*HD + c*8);
        }
        cpa_commit(); cpa_wait<0>();
        __syncthreads();
    }
    uint32_t qh[4][4], ql[4][4];
    #pragma unroll
    for (int kk = 0; kk < 4; kk++){
        fragA(qh[kk], sb,           16*wq, 16*kk, FB, lane);
        fragA(ql[kk], sb + 2*FTILE, 16*wq, 16*kk, FB, lane);
    }
    __syncthreads();

    auto stage = [&](int j0, int buf){
        uint32_t s = sb + buf*FBUF;
        #pragma unroll
        for (int i = 0; i < 8; i++){
            int idx = tid + 256*i;
            int arr = idx >> 9, rem = idx & 511, r = rem >> 3, c = rem & 7;
            const __nv_bfloat16* g = arr==0?Khg:arr==1?Klg:arr==2?Vhg:Vlg;
            cpa16(s + arr*FTILE + r*FB + c*16, g + (size_t)(j0+r)*HD + c*8);
        }
        cpa_commit();
    };

    float m0r = -1e30f, m1r = -1e30f, l0 = 0.f, l1 = 0.f;
    float oc[8][4] = {};
    const float scale = 0.03125f;
    stage(0,0); stage(64,1);

    for (int it = 0; it < NIT; it++){
        if (it+1 < NIT) cpa_wait<1>(); else cpa_wait<0>();
        __syncthreads();
        uint32_t kb  = sb + (it&1)*FBUF;
        uint32_t klb = kb + FTILE, vb = kb + 2*FTILE, vlb = kb + 3*FTILE;

        float sc[8][4] = {};
        #pragma unroll
        for (int kk = 0; kk < 4; kk++){
            int k0 = 16*kk;
            uint32_t khf[4][4], klf[4][4];
            #pragma unroll
            for (int g = 0; g < 4; g++){
                fragB(khf[g], kb,  16*g, k0, FB, lane);
                fragB(klf[g], klb, 16*g, k0, FB, lane);
            }
            #pragma unroll
            for (int nf = 0; nf < 8; nf++){
                const uint32_t* bhp = &khf[nf>>1][(nf&1)*2];
                const uint32_t* blp = &klf[nf>>1][(nf&1)*2];
                mma_bf16(sc[nf], qh[kk], bhp);
                mma_bf16(sc[nf], ql[kk], bhp);
                mma_bf16(sc[nf], qh[kk], blp);
            }
        }
        // warp-local online softmax (each thread: rows r0, r0+8)
        float mx0 = -1e30f, mx1 = -1e30f;
        #pragma unroll
        for (int nf = 0; nf < 8; nf++){
            #pragma unroll
            for (int r = 0; r < 4; r++) sc[nf][r] *= scale;
            mx0 = fmaxf(mx0, fmaxf(sc[nf][0], sc[nf][1]));
            mx1 = fmaxf(mx1, fmaxf(sc[nf][2], sc[nf][3]));
        }
        mx0 = fmaxf(mx0, __shfl_xor_sync(~0u, mx0, 1));
        mx0 = fmaxf(mx0, __shfl_xor_sync(~0u, mx0, 2));
        mx1 = fmaxf(mx1, __shfl_xor_sync(~0u, mx1, 1));
        mx1 = fmaxf(mx1, __shfl_xor_sync(~0u, mx1, 2));
        float mn0 = fmaxf(m0r, mx0), mn1 = fmaxf(m1r, mx1);
        float al0 = __expf(m0r - mn0), al1 = __expf(m1r - mn1);
        m0r = mn0; m1r = mn1;

        uint32_t ph[4][4], pl[4][4];
        float rs0 = 0.f, rs1 = 0.f;
        #pragma unroll
        for (int tc = 0; tc < 4; tc++){
            float pa[4], pb[4];
            pa[0]=__expf(sc[2*tc][0]-mn0);   pa[1]=__expf(sc[2*tc][1]-mn0);
            pa[2]=__expf(sc[2*tc][2]-mn1);   pa[3]=__expf(sc[2*tc][3]-mn1);
            pb[0]=__expf(sc[2*tc+1][0]-mn0); pb[1]=__expf(sc[2*tc+1][1]-mn0);
            pb[2]=__expf(sc[2*tc+1][2]-mn1); pb[3]=__expf(sc[2*tc+1][3]-mn1);
            rs0 += pa[0]+pa[1]+pb[0]+pb[1];
            rs1 += pa[2]+pa[3]+pb[2]+pb[3];
            __nv_bfloat16 h0=__float2bfloat16(pa[0]), h1=__float2bfloat16(pa[1]),
                          h2=__float2bfloat16(pa[2]), h3=__float2bfloat16(pa[3]);
            __nv_bfloat16 g0=__float2bfloat16(pb[0]), g1=__float2bfloat16(pb[1]),
                          g2=__float2bfloat16(pb[2]), g3=__float2bfloat16(pb[3]);
            ph[tc][0]=pack2(h0,h1); ph[tc][1]=pack2(h2,h3);
            ph[tc][2]=pack2(g0,g1); ph[tc][3]=pack2(g2,g3);
            pl[tc][0]=pack2(__float2bfloat16(pa[0]-__bfloat162float(h0)),
                            __float2bfloat16(pa[1]-__bfloat162float(h1)));
            pl[tc][1]=pack2(__float2bfloat16(pa[2]-__bfloat162float(h2)),
                            __float2bfloat16(pa[3]-__bfloat162float(h3)));
            pl[tc][2]=pack2(__float2bfloat16(pb[0]-__bfloat162float(g0)),
                            __float2bfloat16(pb[1]-__bfloat162float(g1)));
            pl[tc][3]=pack2(__float2bfloat16(pb[2]-__bfloat162float(g2)),
                            __float2bfloat16(pb[3]-__bfloat162float(g3)));
        }
        rs0 += __shfl_xor_sync(~0u, rs0, 1); rs0 += __shfl_xor_sync(~0u, rs0, 2);
        rs1 += __shfl_xor_sync(~0u, rs1, 1); rs1 += __shfl_xor_sync(~0u, rs1, 2);
        l0 = l0*al0 + rs0; l1 = l1*al1 + rs1;
        #pragma unroll
        for (int nf = 0; nf < 8; nf++){
            oc[nf][0]*=al0; oc[nf][1]*=al0; oc[nf][2]*=al1; oc[nf][3]*=al1;
        }
        #pragma unroll
        for (int tc = 0; tc < 4; tc++){
            #pragma unroll
            for (int g = 0; g < 4; g++){
                uint32_t vh[4], vl[4];
                fragBt(vh, vb,  16*tc, 16*g, FB, lane);
                fragBt(vl, vlb, 16*tc, 16*g, FB, lane);
                mma_bf16(oc[2*g],   ph[tc], &vh[0]);
                mma_bf16(oc[2*g],   pl[tc], &vh[0]);
                mma_bf16(oc[2*g],   ph[tc], &vl[0]);
                mma_bf16(oc[2*g+1], ph[tc], &vh[2]);
                mma_bf16(oc[2*g+1], pl[tc], &vh[2]);
                mma_bf16(oc[2*g+1], ph[tc], &vl[2]);
            }
        }
        __syncthreads();
        if (it+2 < NIT) stage((it+2)*64, it&1);
    }

    float inv0 = 1.f/l0, inv1 = 1.f/l1;
    int b = bh >> 4, h = bh & 15;
    int r0 = s0 + 16*wq + (lane >> 2);
    #pragma unroll
    for (int nf = 0; nf < 8; nf++){
        int col = h*HD + 8*nf + (lane&3)*2;
        size_t oA = ((size_t)b*SEQ + r0)*DM + col;
        store_split2(g_Ch, g_Cl, oA,                 oc[nf][0]*inv0, oc[nf][1]*inv0);
        store_split2(g_Ch, g_Cl, oA + 8*(size_t)DM,  oc[nf][2]*inv1, oc[nf][3]*inv1);
    }
}

// ===========================================================================
// out: out[m,n] = ctx[m,:] . Wo[n,:] + bo[n]; B rows = n (non-trans)
// ===========================================================================
#define OT    (128*144)            // 18432 (both A and B tiles)
#define OSTG  (4*OT)               // 73728
#define OUT_SMEM (2*OSTG)          // 147456

__global__ __launch_bounds__(256) void out_tc(const float* __restrict__ bo,
                                              float* __restrict__ out)
{
    extern __shared__ char sm[];
    const uint32_t sb = smem_u32(sm);
    const int tid = threadIdx.x, lane = tid & 31, wid = tid >> 5;
    const int wr = wid >> 1, wc = wid & 1;
    const int m0 = blockIdx.x*128, n0 = blockIdx.y*128;

    auto stage = [&](int ch, int buf){
        int d0 = ch*64;
        uint32_t s = sb + buf*OSTG;
        #pragma unroll
        for (int i = 0; i < 4; i++){
            int idx = tid + 256*i, r = idx >> 3, c = idx & 7;
            cpa16(s + r*144 + c*16,          g_Ch + (size_t)(m0+r)*DM + d0 + c*8);
            cpa16(s + OT + r*144 + c*16,     g_Cl + (size_t)(m0+r)*DM + d0 + c*8);
            cpa16(s + 2*OT + r*144 + c*16,   g_Woh + (size_t)(n0+r)*DM + d0 + c*8);
            cpa16(s + 3*OT + r*144 + c*16,   g_Wol + (size_t)(n0+r)*DM + d0 + c*8);
        }
        cpa_commit();
    };

    float acc[2][8][4] = {};
    stage(0,0); stage(1,1);
    for (int ch = 0; ch < 16; ch++){
        if (ch+1 < 16) cpa_wait<1>(); else cpa_wait<0>();
        __syncthreads();
        uint32_t ab = sb + (ch&1)*OSTG, bb = ab + 2*OT;
        #pragma unroll
        for (int kk = 0; kk < 4; kk++){
            int k0 = 16*kk;
            uint32_t ah[2][4], al[2][4], bh[4][4], bl[4][4];
            fragA(ah[0], ab,      32*wr,    k0, 144, lane);
            fragA(ah[1], ab,      32*wr+16, k0, 144, lane);
            fragA(al[0], ab+OT,   32*wr,    k0, 144, lane);
            fragA(al[1], ab+OT,   32*wr+16, k0, 144, lane);
            #pragma unroll
            for (int g = 0; g < 4; g++){
                fragB(bh[g], bb,      64*wc+16*g, k0, 144, lane);
                fragB(bl[g], bb+OT,   64*wc+16*g, k0, 144, lane);
            }
            #pragma unroll
            for (int mg = 0; mg < 2; mg++)
                #pragma unroll
                for (int nf = 0; nf < 8; nf++){
                    const uint32_t* bhp = &bh[nf>>1][(nf&1)*2];
                    const uint32_t* blp = &bl[nf>>1][(nf&1)*2];
                    mma_bf16(acc[mg][nf], ah[mg], bhp);
                    mma_bf16(acc[mg][nf], al[mg], bhp);
                    mma_bf16(acc[mg][nf], ah[mg], blp);
                }
        }
        __syncthreads();
        if (ch+2 < 16) stage(ch+2, ch&1);
    }
    #pragma unroll
    for (int mg = 0; mg < 2; mg++)
        #pragma unroll
        for (int nf = 0; nf < 8; nf++){
            int n = n0 + 64*wc + 8*nf + (lane&3)*2;
            float b0 = bo[n], b1 = bo[n+1];
            int mA = m0 + 32*wr + 16*mg + (lane>>2);
            *(float2*)(out + (size_t)mA*DM + n)
                = make_float2(acc[mg][nf][0] + b0, acc[mg][nf][1] + b1);
            *(float2*)(out + (size_t)(mA+8)*DM + n)
                = make_float2(acc[mg][nf][2] + b0, acc[mg][nf][3] + b1);
        }
}

// ===========================================================================
extern "C" void kernel_launch(void* const* d_in, const int* in_sizes, int n_in,
                              void* d_out, int out_size)
{
    const float* q  = (const float*)d_in[0];
    const float* k  = (const float*)d_in[1];
    const float* v  = (const float*)d_in[2];
    const float* Wq = (const float*)d_in[3];
    const float* Wk = (const float*)d_in[4];
    const float* Wv = (const float*)d_in[5];
    const float* Wo = (const float*)d_in[6];
    const float* bo = (const float*)d_in[7];
    float* out = (float*)d_out;

    cudaFuncSetAttribute(proj_tc,  cudaFuncAttributeMaxDynamicSharedMemorySize, PROJ_SMEM);
    cudaFuncSetAttribute(flash_tc, cudaFuncAttributeMaxDynamicSharedMemorySize, FLASH_SMEM);
    cudaFuncSetAttribute(out_tc,   cudaFuncAttributeMaxDynamicSharedMemorySize, OUT_SMEM);

    prep<<<dim3(128,1,7), 256>>>(q, k, v, Wq, Wk, Wv, Wo);

    dim3 gp(NT/128, DM/128, 3);
    proj_tc<<<gp, 256, PROJ_SMEM>>>();

    dim3 gf(SEQ/128, BATCH*NH);
    flash_tc<<<gf, 256, FLASH_SMEM>>>();

    dim3 go(NT/128, DM/128);
    out_tc<<<go, 256, OUT_SMEM>>>(bo, out);
}